// round 9
// baseline (speedup 1.0000x reference)
#include <cuda_runtime.h>
#include <cuda_bf16.h>
#include <math.h>
#include <stdint.h>

// ---------------------------------------------------------------------------
// Problem constants
// ---------------------------------------------------------------------------
#define VOCAB 32000
#define EDIM  1024
#define MDIM  4096
#define NLAY  4
#define BATCH 4
#define SEQ   2048
#define NROWS (BATCH*SEQ)   // 8192

// ---------------------------------------------------------------------------
// Static device scratch
// ---------------------------------------------------------------------------
__device__ __align__(256) __nv_bfloat16 g_hhi [NROWS * EDIM];
__device__ __align__(256) __nv_bfloat16 g_hlo [NROWS * EDIM];
__device__ __align__(256) __nv_bfloat16 g_phi [NROWS * EDIM];   // mlp ping
__device__ __align__(256) __nv_bfloat16 g_plo [NROWS * EDIM];
__device__ __align__(256) __nv_bfloat16 g_qkvhi[(size_t)NROWS * 3 * EDIM];
__device__ __align__(256) __nv_bfloat16 g_qkvlo[(size_t)NROWS * 3 * EDIM];
__device__ __align__(256) __nv_bfloat16 g_vthi[(size_t)BATCH * EDIM * SEQ];
__device__ __align__(256) __nv_bfloat16 g_vtlo[(size_t)BATCH * EDIM * SEQ];
__device__ __align__(256) float         g_sc  [(size_t)BATCH * SEQ * SEQ];
__device__ __align__(256) __nv_bfloat16 g_whi [(size_t)BATCH * SEQ * SEQ];
__device__ __align__(256) __nv_bfloat16 g_wlo [(size_t)BATCH * SEQ * SEQ];
__device__ __align__(256) __nv_bfloat16 g_mhi [(size_t)NROWS * MDIM];
__device__ __align__(256) __nv_bfloat16 g_mlo [(size_t)NROWS * MDIM];
__device__ __align__(256) __nv_bfloat16 g_wqkvt[(size_t)2 * 3 * EDIM * EDIM]; // [hi(3E,E)|lo(3E,E)]
__device__ __align__(256) __nv_bfloat16 g_w1t [(size_t)2 * NLAY * MDIM * EDIM];
__device__ __align__(256) __nv_bfloat16 g_w2t [(size_t)2 * NLAY * EDIM * MDIM];
__device__ __align__(256) float         g_bqkv[3 * EDIM];

// ---------------------------------------------------------------------------
// PTX helpers (valid at plain compute_103 target)
// ---------------------------------------------------------------------------
#define CP_ASYNC16(dst, src) \
    asm volatile("cp.async.cg.shared.global [%0], [%1], 16;" :: "r"(dst), "l"(src))
#define CP_COMMIT() asm volatile("cp.async.commit_group;" ::: "memory")
#define CP_WAIT(n)  asm volatile("cp.async.wait_group %0;" :: "n"(n) : "memory")

__device__ __forceinline__ uint32_t smem_u32(const void* p) {
    uint32_t a;
    asm("{ .reg .u64 t; cvta.to.shared.u64 t, %1; cvt.u32.u64 %0, t; }"
        : "=r"(a) : "l"(p));
    return a;
}

#define LDSM4(R, A) \
    asm volatile("ldmatrix.sync.aligned.m8n8.x4.shared.b16 {%0,%1,%2,%3}, [%4];" \
        : "=r"((R)[0]), "=r"((R)[1]), "=r"((R)[2]), "=r"((R)[3]) : "r"(A))

__device__ __forceinline__ void mma16816(float* c, const uint32_t* a, const uint32_t* b) {
    asm volatile(
        "mma.sync.aligned.m16n8k16.row.col.f32.bf16.bf16.f32 "
        "{%0,%1,%2,%3}, {%4,%5,%6,%7}, {%8,%9}, {%0,%1,%2,%3};"
        : "+f"(c[0]), "+f"(c[1]), "+f"(c[2]), "+f"(c[3])
        : "r"(a[0]), "r"(a[1]), "r"(a[2]), "r"(a[3]), "r"(b[0]), "r"(b[1]));
}

__device__ __forceinline__ void split2(float v, __nv_bfloat16& hi, __nv_bfloat16& lo) {
    hi = __float2bfloat16(v);
    lo = __float2bfloat16(v - __bfloat162float(hi));
}

// packed split: hp = {bf16(x1)<<16 | bf16(x0)}, lp = residuals, rn rounding
__device__ __forceinline__ void split_pack(float x0, float x1, uint32_t& hp, uint32_t& lp) {
    uint32_t h;
    asm("cvt.rn.bf16x2.f32 %0, %1, %2;" : "=r"(h) : "f"(x1), "f"(x0));
    const float h0 = __uint_as_float(h << 16);
    const float h1 = __uint_as_float(h & 0xFFFF0000u);
    asm("cvt.rn.bf16x2.f32 %0, %1, %2;" : "=r"(lp) : "f"(x1 - h1), "f"(x0 - h0));
    hp = h;
}

struct GP {
    const __nv_bfloat16 *Ahi, *Alo, *Bhi, *Blo;
    const float* bias;
    float* outF;
    __nv_bfloat16 *outHi, *outLo;
    int K, ldA, ldB, ldC;
    size_t szA, szB, szC;
    float scale;
    int relu;
    int maskSkip;
    int triK;
};

// ===========================================================================
// Persistent GEMM (uniform shapes): tile 128x128, 8 warps (64x32), BK=32,
// NSTG=2, 2 CTAs/SM (barrier/latency stalls covered by co-resident CTA).
// ===========================================================================
#define PBK     32
#define PPITCH  40                 // u16 per row (32 data + 8 pad) = 80 B
#define PTILE   (128*PPITCH*2)     // 10240 B per operand tile
#define PSTG    (4*PTILE)          // 40960 B per stage (Ahi,Alo,Bhi,Blo)
#define PSMEM   (2*PSTG)           // 81920 B

__global__ void __launch_bounds__(256, 2) tgemm_persist(GP p, int Mt, int Nt, int nCTA)
{
    extern __shared__ char smem[];
    const uint32_t sbase = smem_u32(smem);
    const int tiles = Mt * Nt;
    const int bid = blockIdx.x;
    if (bid >= tiles) return;

    const int tid  = threadIdx.x;
    const int wid  = tid >> 5;
    const int lane = tid & 31;
    const int g    = lane >> 2;
    const int tg   = lane & 3;
    const int wm0  = (wid & 1) * 64;    // warp m offset
    const int wn0  = (wid >> 1) * 32;   // warp n offset
    const int l15  = lane & 15;
    const uint32_t aoff = (uint32_t)(((wm0 + l15) * PPITCH + ((lane >> 4) * 8)) * 2);
    const int bN  = ((lane & 16) >> 1) + (lane & 7);
    const uint32_t boff = (uint32_t)(((wn0 + bN) * PPITCH + (lane & 8)) * 2);

    const size_t rsA = (size_t)p.ldA * 2;
    const size_t rsB = (size_t)p.ldB * 2;
    const int NC = p.K / PBK;
    const int myTiles = (tiles - 1 - bid) / nCTA + 1;
    const int totalC = myTiles * NC;

    // cp.async mapping: 4 threads/row (64B), 256 threads -> 64 rows/pass
    const int r0c = tid >> 2;
    const int ccc = (tid & 3) * 16;

    // ---- load cursor (streams continuously across tiles) ----
    int tl_l = bid, c_l = 0, il = 0;
    const char *laH, *laL, *lbH, *lbL;
    {
        int n = tl_l % Nt, m = tl_l / Nt;
        laH = (const char*)p.Ahi + (size_t)(m * 128) * rsA;
        laL = (const char*)p.Alo + (size_t)(m * 128) * rsA;
        lbH = (const char*)p.Bhi + (size_t)(n * 128) * rsB;
        lbL = (const char*)p.Blo + (size_t)(n * 128) * rsB;
    }
    auto issue_load = [&]() {
        const uint32_t sb = sbase + (uint32_t)(il & 1) * PSTG;
        const size_t kb = (size_t)c_l * 64 + ccc;
        #pragma unroll
        for (int h = 0; h < 2; h++) {
            const int row = r0c + h * 64;
            const uint32_t doff = row * (PPITCH*2) + ccc;
            const size_t goA = (size_t)row * rsA + kb;
            const size_t goB = (size_t)row * rsB + kb;
            CP_ASYNC16(sb + 0*PTILE + doff, laH + goA);
            CP_ASYNC16(sb + 1*PTILE + doff, laL + goA);
            CP_ASYNC16(sb + 2*PTILE + doff, lbH + goB);
            CP_ASYNC16(sb + 3*PTILE + doff, lbL + goB);
        }
        CP_COMMIT();
        il++; c_l++;
        if (c_l == NC) {
            c_l = 0; tl_l += nCTA;
            if (tl_l < tiles) {
                int n = tl_l % Nt, m = tl_l / Nt;
                laH = (const char*)p.Ahi + (size_t)(m * 128) * rsA;
                laL = (const char*)p.Alo + (size_t)(m * 128) * rsA;
                lbH = (const char*)p.Bhi + (size_t)(n * 128) * rsB;
                lbL = (const char*)p.Blo + (size_t)(n * 128) * rsB;
            }
        }
    };

    issue_load();
    if (totalC > 1) issue_load();

    float acc[4][4][4];
    #pragma unroll
    for (int a = 0; a < 4; a++)
        #pragma unroll
        for (int b = 0; b < 4; b++)
            #pragma unroll
            for (int q = 0; q < 4; q++) acc[a][b][q] = 0.f;

    int i = 0;
    for (int tl = bid; tl < tiles; tl += nCTA) {
        const int m0 = (tl / Nt) * 128;
        const int n0 = (tl % Nt) * 128;

        for (int c = 0; c < NC; c++, i++) {
            if (i + 1 < totalC) CP_WAIT(1);
            else                CP_WAIT(0);
            __syncthreads();

            const uint32_t sb = sbase + (uint32_t)(i & 1) * PSTG;
            #pragma unroll
            for (int kk = 0; kk < PBK; kk += 16) {
                uint32_t ah[4][4], al[4][4];
                #pragma unroll
                for (int mt = 0; mt < 4; mt++) {
                    const uint32_t ao = sb + aoff + mt*(16*PPITCH*2) + kk*2;
                    LDSM4(ah[mt], ao);
                    LDSM4(al[mt], ao + PTILE);
                }
                #pragma unroll
                for (int ntp = 0; ntp < 2; ntp++) {
                    uint32_t bh[4], bl[4];
                    const uint32_t bo = sb + 2*PTILE + boff + ntp*(16*PPITCH*2) + kk*2;
                    LDSM4(bh, bo);
                    LDSM4(bl, bo + PTILE);
                    #pragma unroll
                    for (int mt = 0; mt < 4; mt++)
                        #pragma unroll
                        for (int nt = 0; nt < 2; nt++)
                            mma16816(acc[mt][ntp*2+nt], ah[mt], &bh[nt*2]);
                    #pragma unroll
                    for (int mt = 0; mt < 4; mt++)
                        #pragma unroll
                        for (int nt = 0; nt < 2; nt++)
                            mma16816(acc[mt][ntp*2+nt], ah[mt], &bl[nt*2]);
                    #pragma unroll
                    for (int mt = 0; mt < 4; mt++)
                        #pragma unroll
                        for (int nt = 0; nt < 2; nt++)
                            mma16816(acc[mt][ntp*2+nt], al[mt], &bh[nt*2]);
                }
            }

            __syncthreads();
            if (il < totalC) issue_load();   // refills the stage just consumed
        }

        // ---- epilogue (no smem; overlaps next tile's in-flight loads) ----
        float2 bb[4];
        #pragma unroll
        for (int nt = 0; nt < 4; nt++) {
            if (p.bias) bb[nt] = *(const float2*)(p.bias + n0 + wn0 + nt*8 + tg*2);
            else        bb[nt] = make_float2(0.f, 0.f);
        }
        #pragma unroll
        for (int mt = 0; mt < 4; mt++) {
            #pragma unroll
            for (int half = 0; half < 2; half++) {
                const int r = m0 + wm0 + mt*16 + g + half*8;
                #pragma unroll
                for (int nt = 0; nt < 4; nt++) {
                    float x0 = acc[mt][nt][half*2+0] * p.scale + bb[nt].x;
                    float x1 = acc[mt][nt][half*2+1] * p.scale + bb[nt].y;
                    if (p.relu) { x0 = fmaxf(x0, 0.f); x1 = fmaxf(x1, 0.f); }
                    const size_t o = (size_t)r * p.ldC + n0 + wn0 + nt*8 + tg*2;
                    if (p.outF)
                        *(float2*)(p.outF + o) = make_float2(x0, x1);
                    if (p.outHi) {
                        uint32_t hp, lp;
                        split_pack(x0, x1, hp, lp);
                        *(uint32_t*)(p.outHi + o) = hp;
                        *(uint32_t*)(p.outLo + o) = lp;
                    }
                    acc[mt][nt][half*2+0] = 0.f;
                    acc[mt][nt][half*2+1] = 0.f;
                }
            }
        }
    }
}

// ===========================================================================
// Attention GEMM (maskSkip / triK / batched): tile 128x256, BK=64, NSTG=2
// ===========================================================================
#define BK      64
#define APITCH  72
#define TILEA   (128*APITCH*2)
#define TILEBB  (256*APITCH*2)
#define STGB    (2*TILEA + 2*TILEBB)
#define NSTG    2
#define GEMM_SMEM (NSTG*STGB)      // 221184

#define OFF_AHI 0
#define OFF_ALO (TILEA)
#define OFF_BHI (2*TILEA)
#define OFF_BLO (2*TILEA + TILEBB)

__global__ void __launch_bounds__(256, 1) tgemm(GP p)
{
    const int m0 = blockIdx.y * 128;
    const int n0 = blockIdx.x * 256;
    if (p.maskSkip && (n0 + 256 <= m0)) return;

    extern __shared__ char smem[];
    const uint32_t sbase = smem_u32(smem);

    const int tid  = threadIdx.x;
    const int wid  = tid >> 5;
    const int lane = tid & 31;
    const int g    = lane >> 2;
    const int tg   = lane & 3;
    const int wm0 = (wid & 1) * 64;
    const int wn0 = (wid >> 1) * 64;

    const size_t zA = (size_t)blockIdx.z * p.szA;
    const size_t zB = (size_t)blockIdx.z * p.szB;
    const size_t zC = (size_t)blockIdx.z * p.szC;

    const char* aHi = (const char*)(p.Ahi + zA + (size_t)m0 * p.ldA);
    const char* aLo = (const char*)(p.Alo + zA + (size_t)m0 * p.ldA);
    const char* bHi = (const char*)(p.Bhi + zB + (size_t)n0 * p.ldB);
    const char* bLo = (const char*)(p.Blo + zB + (size_t)n0 * p.ldB);
    const size_t rsA = (size_t)p.ldA * 2;
    const size_t rsB = (size_t)p.ldB * 2;

    const int l15 = lane & 15;
    const uint32_t aoff = (uint32_t)(((wm0 + l15) * APITCH + ((lane >> 4) * 8)) * 2);
    const int bN  = ((lane & 16) >> 1) + (lane & 7);
    const uint32_t boff = (uint32_t)(((wn0 + bN) * APITCH + (lane & 8)) * 2);

    const int r0c = tid >> 3;
    const int ccc = (tid & 7) * 16;

    const int NC = p.K / BK;
    const int c0 = p.triK ? (m0 / BK) : 0;
    const int NCr = NC - c0;

    auto load_chunk = [&](int c, int stg) {
        const size_t kb = (size_t)c * BK * 2;
        const uint32_t sb = sbase + stg * STGB;
        #pragma unroll
        for (int h = 0; h < 4; h++) {
            const int row = r0c + h * 32;
            const uint32_t doff = row * (APITCH*2) + ccc;
            const size_t goA = (size_t)row * rsA + kb + ccc;
            CP_ASYNC16(sb + OFF_AHI + doff, aHi + goA);
            CP_ASYNC16(sb + OFF_ALO + doff, aLo + goA);
        }
        #pragma unroll
        for (int h = 0; h < 8; h++) {
            const int row = r0c + h * 32;
            const uint32_t doff = row * (APITCH*2) + ccc;
            const size_t goB = (size_t)row * rsB + kb + ccc;
            CP_ASYNC16(sb + OFF_BHI + doff, bHi + goB);
            CP_ASYNC16(sb + OFF_BLO + doff, bLo + goB);
        }
        CP_COMMIT();
    };

    float acc[4][8][4];
    #pragma unroll
    for (int a = 0; a < 4; a++)
        #pragma unroll
        for (int b = 0; b < 8; b++)
            #pragma unroll
            for (int q = 0; q < 4; q++) acc[a][b][q] = 0.f;

    load_chunk(c0 + 0, 0);
    load_chunk(c0 + 1, 1);

    for (int cr = 0; cr < NCr; cr++) {
        const int stg = cr & 1;
        if (cr + 1 < NCr) CP_WAIT(1);
        else              CP_WAIT(0);
        __syncthreads();

        const uint32_t sb = sbase + stg * STGB;
        #pragma unroll
        for (int kk = 0; kk < BK; kk += 16) {
            uint32_t ah[4][4], al[4][4];
            #pragma unroll
            for (int mt = 0; mt < 4; mt++) {
                const uint32_t ao = sb + aoff + mt*(16*APITCH*2) + kk*2;
                LDSM4(ah[mt], ao);
                LDSM4(al[mt], ao + TILEA);
            }
            #pragma unroll
            for (int ntp = 0; ntp < 4; ntp++) {
                uint32_t bh[4], bl[4];
                const uint32_t bo = sb + OFF_BHI + boff + ntp*(16*APITCH*2) + kk*2;
                LDSM4(bh, bo);
                LDSM4(bl, bo + TILEBB);
                #pragma unroll
                for (int mt = 0; mt < 4; mt++)
                    #pragma unroll
                    for (int nt = 0; nt < 2; nt++)
                        mma16816(acc[mt][ntp*2+nt], ah[mt], &bh[nt*2]);
                #pragma unroll
                for (int mt = 0; mt < 4; mt++)
                    #pragma unroll
                    for (int nt = 0; nt < 2; nt++)
                        mma16816(acc[mt][ntp*2+nt], ah[mt], &bl[nt*2]);
                #pragma unroll
                for (int mt = 0; mt < 4; mt++)
                    #pragma unroll
                    for (int nt = 0; nt < 2; nt++)
                        mma16816(acc[mt][ntp*2+nt], al[mt], &bh[nt*2]);
            }
        }

        __syncthreads();
        if (cr + NSTG < NCr) load_chunk(c0 + cr + NSTG, stg);
    }

    float2 bb[8];
    #pragma unroll
    for (int nt = 0; nt < 8; nt++) {
        if (p.bias) bb[nt] = *(const float2*)(p.bias + n0 + wn0 + nt*8 + tg*2);
        else        bb[nt] = make_float2(0.f, 0.f);
    }
    #pragma unroll
    for (int mt = 0; mt < 4; mt++) {
        #pragma unroll
        for (int half = 0; half < 2; half++) {
            const int r = m0 + wm0 + mt*16 + g + half*8;
            #pragma unroll
            for (int nt = 0; nt < 8; nt++) {
                float x0 = acc[mt][nt][half*2+0] * p.scale + bb[nt].x;
                float x1 = acc[mt][nt][half*2+1] * p.scale + bb[nt].y;
                if (p.relu) { x0 = fmaxf(x0, 0.f); x1 = fmaxf(x1, 0.f); }
                const size_t o = zC + (size_t)r * p.ldC + n0 + wn0 + nt*8 + tg*2;
                if (p.outF)
                    *(float2*)(p.outF + o) = make_float2(x0, x1);
                if (p.outHi) {
                    uint32_t hp, lp;
                    split_pack(x0, x1, hp, lp);
                    *(uint32_t*)(p.outHi + o) = hp;
                    *(uint32_t*)(p.outLo + o) = lp;
                }
            }
        }
    }
}

// ---------------------------------------------------------------------------
// Embedding gather + hi/lo split
// ---------------------------------------------------------------------------
__global__ void embed_split(const int* __restrict__ x, const float* __restrict__ emb,
                            __nv_bfloat16* __restrict__ hhi, __nv_bfloat16* __restrict__ hlo)
{
    const int r = blockIdx.x;
    const int row = x[r];
    const float4 f = ((const float4*)(emb + (size_t)row * EDIM))[threadIdx.x];
    const size_t o = (size_t)r * EDIM + threadIdx.x * 4;
    uint32_t hp, lp;
    split_pack(f.x, f.y, hp, lp);
    *(uint32_t*)(hhi + o)     = hp;  *(uint32_t*)(hlo + o)     = lp;
    split_pack(f.z, f.w, hp, lp);
    *(uint32_t*)(hhi + o + 2) = hp;  *(uint32_t*)(hlo + o + 2) = lp;
}

// ---------------------------------------------------------------------------
// Weight transpose + hi/lo split: fp32 [R,C] -> bf16 [C,R]
// ---------------------------------------------------------------------------
__global__ void transpose_split(const float* __restrict__ src,
                                __nv_bfloat16* __restrict__ dhi,
                                __nv_bfloat16* __restrict__ dlo,
                                int R, int C, size_t szSrc, size_t szDst)
{
    __shared__ float t[32][33];
    src += (size_t)blockIdx.z * szSrc;
    dhi += (size_t)blockIdx.z * szDst;
    dlo += (size_t)blockIdx.z * szDst;
    const int c0 = blockIdx.x * 32, r0 = blockIdx.y * 32;
    const int tx = threadIdx.x, ty = threadIdx.y;
    #pragma unroll
    for (int j = 0; j < 4; j++)
        t[ty + j*8][tx] = src[(size_t)(r0 + ty + j*8) * C + c0 + tx];
    __syncthreads();
    #pragma unroll
    for (int j = 0; j < 4; j++) {
        const float v = t[tx][ty + j*8];
        __nv_bfloat16 h, l;
        split2(v, h, l);
        const size_t o = (size_t)(c0 + ty + j*8) * R + r0 + tx;
        dhi[o] = h; dlo[o] = l;
    }
}

// ---------------------------------------------------------------------------
// V transpose from fused QKV buffer (bf16 hi/lo): [S, cols@2048..3071] -> [E,S]
// ---------------------------------------------------------------------------
__global__ void transpose_v(const uint16_t* __restrict__ qkvhi,
                            const uint16_t* __restrict__ qkvlo,
                            uint16_t* __restrict__ dhi, uint16_t* __restrict__ dlo)
{
    __shared__ uint32_t t[32][33];
    const int b = blockIdx.z;
    const int c0 = blockIdx.x * 32;   // e index
    const int r0 = blockIdx.y * 32;   // s index
    const int tx = threadIdx.x, ty = threadIdx.y;
    const size_t srcBase = (size_t)b * SEQ * (3*EDIM) + 2048;
    #pragma unroll
    for (int j = 0; j < 4; j++) {
        const size_t idx = srcBase + (size_t)(r0 + ty + j*8) * (3*EDIM) + c0 + tx;
        t[ty + j*8][tx] = (uint32_t)qkvhi[idx] | ((uint32_t)qkvlo[idx] << 16);
    }
    __syncthreads();
    const size_t dstBase = (size_t)b * EDIM * SEQ;
    #pragma unroll
    for (int j = 0; j < 4; j++) {
        const uint32_t v = t[tx][ty + j*8];
        const size_t o = dstBase + (size_t)(c0 + ty + j*8) * SEQ + r0 + tx;
        dhi[o] = (uint16_t)(v & 0xFFFF);
        dlo[o] = (uint16_t)(v >> 16);
    }
}

// ---------------------------------------------------------------------------
// Masked softmax (keep t >= s), fp32 in -> bf16 hi/lo out, single global read
// ---------------------------------------------------------------------------
__global__ void __launch_bounds__(256) softmax_split(const float* __restrict__ sc,
                                                     __nv_bfloat16* __restrict__ whi,
                                                     __nv_bfloat16* __restrict__ wlo)
{
    const int s = blockIdx.x, b = blockIdx.y;
    const size_t base = ((size_t)b * SEQ + s) * SEQ;
    const float* row = sc + base;
    const int tid = threadIdx.x;
    __shared__ float red[256];

    float rv[8];
    float m = -1e30f;
    {
        int j = 0;
        for (int t = s + tid; t < SEQ; t += 256, j++) {
            rv[j] = row[t];
            m = fmaxf(m, rv[j]);
        }
    }
    red[tid] = m; __syncthreads();
    #pragma unroll
    for (int o = 128; o > 0; o >>= 1) {
        if (tid < o) red[tid] = fmaxf(red[tid], red[tid + o]);
        __syncthreads();
    }
    m = red[0]; __syncthreads();

    float ev[8];
    float sum = 0.f;
    {
        int j = 0;
        for (int t = s + tid; t < SEQ; t += 256, j++) {
            const float e = expf(rv[j] - m);
            ev[j] = e;
            sum += e;
        }
    }
    red[tid] = sum; __syncthreads();
    #pragma unroll
    for (int o = 128; o > 0; o >>= 1) {
        if (tid < o) red[tid] += red[tid + o];
        __syncthreads();
    }
    const float inv = 1.f / red[0];

    for (int t = tid; t < s; t += 256) {
        whi[base + t] = __float2bfloat16(0.f);
        wlo[base + t] = __float2bfloat16(0.f);
    }
    {
        int j = 0;
        for (int t = s + tid; t < SEQ; t += 256, j++) {
            __nv_bfloat16 h, l;
            split2(ev[j] * inv, h, l);
            whi[base + t] = h;
            wlo[base + t] = l;
        }
    }
}

// ---------------------------------------------------------------------------
// Host
// ---------------------------------------------------------------------------
template <typename T>
static T* sym(const void* s) { void* p = nullptr; cudaGetSymbolAddress(&p, s); return (T*)p; }

extern "C" void kernel_launch(void* const* d_in, const int* in_sizes, int n_in,
                              void* d_out, int out_size)
{
    const int*   x   = (const int*)  d_in[0];
    const float* emb = (const float*)d_in[1];
    const float* Wq  = (const float*)d_in[2];
    const float* bq  = (const float*)d_in[3];
    const float* Wk  = (const float*)d_in[4];
    const float* bk  = (const float*)d_in[5];
    const float* Wv  = (const float*)d_in[6];
    const float* bv  = (const float*)d_in[7];
    const float* W1  = (const float*)d_in[8];
    const float* b1  = (const float*)d_in[9];
    const float* W2  = (const float*)d_in[10];
    const float* b2  = (const float*)d_in[11];
    float* out = (float*)d_out;

    static int nsm = 0;
    if (nsm == 0) {
        cudaDeviceGetAttribute(&nsm, cudaDevAttrMultiProcessorCount, 0);
        cudaFuncSetAttribute(tgemm, cudaFuncAttributeMaxDynamicSharedMemorySize, GEMM_SMEM);
        cudaFuncSetAttribute(tgemm_persist, cudaFuncAttributeMaxDynamicSharedMemorySize, PSMEM);
    }

    __nv_bfloat16* hhi  = sym<__nv_bfloat16>(g_hhi);
    __nv_bfloat16* hlo  = sym<__nv_bfloat16>(g_hlo);
    __nv_bfloat16* phi  = sym<__nv_bfloat16>(g_phi);
    __nv_bfloat16* plo  = sym<__nv_bfloat16>(g_plo);
    __nv_bfloat16* qkvhi= sym<__nv_bfloat16>(g_qkvhi);
    __nv_bfloat16* qkvlo= sym<__nv_bfloat16>(g_qkvlo);
    __nv_bfloat16* vthi = sym<__nv_bfloat16>(g_vthi);
    __nv_bfloat16* vtlo = sym<__nv_bfloat16>(g_vtlo);
    float*         sc   = sym<float>(g_sc);
    __nv_bfloat16* whi  = sym<__nv_bfloat16>(g_whi);
    __nv_bfloat16* wlo  = sym<__nv_bfloat16>(g_wlo);
    __nv_bfloat16* mhi  = sym<__nv_bfloat16>(g_mhi);
    __nv_bfloat16* mlo  = sym<__nv_bfloat16>(g_mlo);
    __nv_bfloat16* wqkvt= sym<__nv_bfloat16>(g_wqkvt);
    __nv_bfloat16* w1t  = sym<__nv_bfloat16>(g_w1t);
    __nv_bfloat16* w2t  = sym<__nv_bfloat16>(g_w2t);
    float*         bqkv = sym<float>(g_bqkv);

    const size_t EE = (size_t)EDIM * EDIM;
    const size_t EM = (size_t)EDIM * MDIM;
    __nv_bfloat16* wqkvtHi = wqkvt;
    __nv_bfloat16* wqkvtLo = wqkvt + 3*EE;

    cudaMemcpyAsync(bqkv,            bq, EDIM*sizeof(float), cudaMemcpyDeviceToDevice);
    cudaMemcpyAsync(bqkv + EDIM,     bk, EDIM*sizeof(float), cudaMemcpyDeviceToDevice);
    cudaMemcpyAsync(bqkv + 2*EDIM,   bv, EDIM*sizeof(float), cudaMemcpyDeviceToDevice);

    dim3 tb(32, 8);
    transpose_split<<<dim3(EDIM/32, EDIM/32, 1), tb>>>(Wq, wqkvtHi + 0*EE, wqkvtLo + 0*EE, EDIM, EDIM, 0, 0);
    transpose_split<<<dim3(EDIM/32, EDIM/32, 1), tb>>>(Wk, wqkvtHi + 1*EE, wqkvtLo + 1*EE, EDIM, EDIM, 0, 0);
    transpose_split<<<dim3(EDIM/32, EDIM/32, 1), tb>>>(Wv, wqkvtHi + 2*EE, wqkvtLo + 2*EE, EDIM, EDIM, 0, 0);
    embed_split<<<NROWS, 256>>>(x, emb, hhi, hlo);
    transpose_split<<<dim3(MDIM/32, EDIM/32, NLAY), tb>>>(W1, w1t, w1t + (size_t)NLAY*EM, EDIM, MDIM, EM, EM);

    GP p = {};

    // ---- fused QKV (persistent, 2 CTA/SM) ----
    p.Ahi = hhi; p.Alo = hlo; p.Bhi = wqkvtHi; p.Blo = wqkvtLo;
    p.bias = bqkv; p.outHi = qkvhi; p.outLo = qkvlo; p.outF = nullptr;
    p.K = EDIM; p.ldA = EDIM; p.ldB = EDIM; p.ldC = 3*EDIM;
    p.scale = 1.f; p.relu = 0;
    {
        int Mt = NROWS/128, Nt = (3*EDIM)/128;
        int tiles = Mt*Nt;
        int grid = (2*nsm < tiles) ? 2*nsm : tiles;
        tgemm_persist<<<grid, 256, PSMEM>>>(p, Mt, Nt, grid);
    }

    transpose_split<<<dim3(EDIM/32, MDIM/32, NLAY), tb>>>(W2, w2t, w2t + (size_t)NLAY*EM, MDIM, EDIM, EM, EM);
    transpose_v<<<dim3(EDIM/32, SEQ/32, BATCH), tb>>>((const uint16_t*)qkvhi, (const uint16_t*)qkvlo,
                                                      (uint16_t*)vthi, (uint16_t*)vtlo);

    // ---- scores = scale * q k^T ----
    p.Ahi = qkvhi;        p.Alo = qkvlo;
    p.Bhi = qkvhi + EDIM; p.Blo = qkvlo + EDIM;
    p.ldA = 3*EDIM; p.ldB = 3*EDIM; p.ldC = SEQ; p.K = EDIM;
    p.szA = (size_t)SEQ * 3*EDIM; p.szB = (size_t)SEQ * 3*EDIM; p.szC = (size_t)SEQ * SEQ;
    p.bias = nullptr; p.outF = sc; p.outHi = nullptr; p.outLo = nullptr;
    p.scale = 1.f / 32.f; p.relu = 0; p.maskSkip = 1; p.triK = 0;
    tgemm<<<dim3(SEQ/256, SEQ/128, BATCH), 256, GEMM_SMEM>>>(p);

    softmax_split<<<dim3(SEQ, BATCH), 256>>>(sc, whi, wlo);

    // ---- h = relu(w v) ----
    p.Ahi = whi; p.Alo = wlo; p.Bhi = vthi; p.Blo = vtlo;
    p.ldA = SEQ; p.ldB = SEQ; p.ldC = EDIM; p.K = SEQ;
    p.szA = (size_t)SEQ * SEQ; p.szB = (size_t)EDIM * SEQ; p.szC = (size_t)SEQ * EDIM;
    p.bias = nullptr; p.outF = nullptr; p.outHi = hhi; p.outLo = hlo;
    p.scale = 1.f; p.relu = 1; p.maskSkip = 0; p.triK = 1;
    tgemm<<<dim3(EDIM/256, SEQ/128, BATCH), 256, GEMM_SMEM>>>(p);

    // ---- MLP stack (persistent GEMMs, 2 CTA/SM) ----
    p.szA = p.szB = p.szC = 0;
    p.maskSkip = 0; p.triK = 0;
    __nv_bfloat16 *curHi = hhi, *curLo = hlo;
    __nv_bfloat16 *altHi = phi, *altLo = plo;
    for (int i = 0; i < NLAY; i++) {
        p.Ahi = curHi; p.Alo = curLo;
        p.Bhi = w1t + (size_t)i * EM; p.Blo = w1t + (size_t)(NLAY + i) * EM;
        p.ldA = EDIM; p.ldB = EDIM; p.ldC = MDIM; p.K = EDIM;
        p.bias = b1 + (size_t)i * MDIM;
        p.outHi = mhi; p.outLo = mlo; p.outF = nullptr;
        p.scale = 1.f; p.relu = 1;
        {
            int Mt = NROWS/128, Nt = MDIM/128;
            int tiles = Mt*Nt;
            int grid = (2*nsm < tiles) ? 2*nsm : tiles;
            tgemm_persist<<<grid, 256, PSMEM>>>(p, Mt, Nt, grid);
        }

        p.Ahi = mhi; p.Alo = mlo;
        p.Bhi = w2t + (size_t)i * EM; p.Blo = w2t + (size_t)(NLAY + i) * EM;
        p.ldA = MDIM; p.ldB = MDIM; p.ldC = EDIM; p.K = MDIM;
        p.bias = b2 + (size_t)i * EDIM;
        if (i == NLAY - 1) { p.outHi = nullptr; p.outLo = nullptr; p.outF = out; }
        else               { p.outHi = altHi;  p.outLo = altLo;  p.outF = nullptr; }
        {
            int Mt = NROWS/128, Nt = EDIM/128;
            int tiles = Mt*Nt;
            int grid = (2*nsm < tiles) ? 2*nsm : tiles;
            tgemm_persist<<<grid, 256, PSMEM>>>(p, Mt, Nt, grid);
        }

        __nv_bfloat16* t;
        t = curHi; curHi = altHi; altHi = t;
        t = curLo; curLo = altLo; altLo = t;
    }
}

// round 10
// speedup vs baseline: 1.1075x; 1.1075x over previous
#include <cuda_runtime.h>
#include <cuda_bf16.h>
#include <math.h>
#include <stdint.h>

// ---------------------------------------------------------------------------
// Problem constants
// ---------------------------------------------------------------------------
#define VOCAB 32000
#define EDIM  1024
#define MDIM  4096
#define NLAY  4
#define BATCH 4
#define SEQ   2048
#define NROWS (BATCH*SEQ)   // 8192

// ---------------------------------------------------------------------------
// Static device scratch
// ---------------------------------------------------------------------------
__device__ __align__(256) __nv_bfloat16 g_hhi [NROWS * EDIM];
__device__ __align__(256) __nv_bfloat16 g_hlo [NROWS * EDIM];
__device__ __align__(256) __nv_bfloat16 g_phi [NROWS * EDIM];
__device__ __align__(256) __nv_bfloat16 g_plo [NROWS * EDIM];
__device__ __align__(256) __nv_bfloat16 g_qkvhi[(size_t)NROWS * 3 * EDIM];
__device__ __align__(256) __nv_bfloat16 g_qkvlo[(size_t)NROWS * 3 * EDIM];
__device__ __align__(256) __nv_bfloat16 g_vthi[(size_t)BATCH * EDIM * SEQ];
__device__ __align__(256) __nv_bfloat16 g_vtlo[(size_t)BATCH * EDIM * SEQ];
__device__ __align__(256) float         g_sc  [(size_t)BATCH * SEQ * SEQ];
__device__ __align__(256) __nv_bfloat16 g_whi [(size_t)BATCH * SEQ * SEQ];
__device__ __align__(256) __nv_bfloat16 g_wlo [(size_t)BATCH * SEQ * SEQ];
__device__ __align__(256) __nv_bfloat16 g_mhi [(size_t)NROWS * MDIM];
__device__ __align__(256) __nv_bfloat16 g_mlo [(size_t)NROWS * MDIM];
__device__ __align__(256) __nv_bfloat16 g_wqkvt[(size_t)2 * 3 * EDIM * EDIM];
__device__ __align__(256) __nv_bfloat16 g_w1t [(size_t)2 * NLAY * MDIM * EDIM];
__device__ __align__(256) __nv_bfloat16 g_w2t [(size_t)2 * NLAY * EDIM * MDIM];
__device__ __align__(256) float         g_bqkv[3 * EDIM];

// ---------------------------------------------------------------------------
// PTX helpers (valid at plain compute_103 target)
// ---------------------------------------------------------------------------
#define CP_ASYNC16(dst, src) \
    asm volatile("cp.async.cg.shared.global [%0], [%1], 16;" :: "r"(dst), "l"(src))
#define CP_COMMIT() asm volatile("cp.async.commit_group;" ::: "memory")
#define CP_WAIT(n)  asm volatile("cp.async.wait_group %0;" :: "n"(n) : "memory")

__device__ __forceinline__ uint32_t smem_u32(const void* p) {
    uint32_t a;
    asm("{ .reg .u64 t; cvta.to.shared.u64 t, %1; cvt.u32.u64 %0, t; }"
        : "=r"(a) : "l"(p));
    return a;
}

#define LDSM4(R, A) \
    asm volatile("ldmatrix.sync.aligned.m8n8.x4.shared.b16 {%0,%1,%2,%3}, [%4];" \
        : "=r"((R)[0]), "=r"((R)[1]), "=r"((R)[2]), "=r"((R)[3]) : "r"(A))

__device__ __forceinline__ void mma16816(float* c, const uint32_t* a, const uint32_t* b) {
    asm volatile(
        "mma.sync.aligned.m16n8k16.row.col.f32.bf16.bf16.f32 "
        "{%0,%1,%2,%3}, {%4,%5,%6,%7}, {%8,%9}, {%0,%1,%2,%3};"
        : "+f"(c[0]), "+f"(c[1]), "+f"(c[2]), "+f"(c[3])
        : "r"(a[0]), "r"(a[1]), "r"(a[2]), "r"(a[3]), "r"(b[0]), "r"(b[1]));
}

__device__ __forceinline__ void split2(float v, __nv_bfloat16& hi, __nv_bfloat16& lo) {
    hi = __float2bfloat16(v);
    lo = __float2bfloat16(v - __bfloat162float(hi));
}

// packed split: hp = {bf16(x1)<<16 | bf16(x0)}, lp = residuals, rn rounding
__device__ __forceinline__ void split_pack(float x0, float x1, uint32_t& hp, uint32_t& lp) {
    uint32_t h;
    asm("cvt.rn.bf16x2.f32 %0, %1, %2;" : "=r"(h) : "f"(x1), "f"(x0));
    const float h0 = __uint_as_float(h << 16);
    const float h1 = __uint_as_float(h & 0xFFFF0000u);
    asm("cvt.rn.bf16x2.f32 %0, %1, %2;" : "=r"(lp) : "f"(x1 - h1), "f"(x0 - h0));
    hp = h;
}

struct GP {
    const __nv_bfloat16 *Ahi, *Alo, *Bhi, *Blo;
    const float* bias;
    float* outF;
    __nv_bfloat16 *outHi, *outLo;
    int K, ldA, ldB, ldC;
    size_t szA, szB, szC;
    float scale;
    int relu;
    int maskSkip;   // skip tiles fully below diagonal (scores)
    int triK;       // start K at m0 (w@v: w[s,t]=0 for t<s)
};

// ===========================================================================
// GEMM: out = act(scale*(Ahi+Alo)·(Bhi+Blo)^T + bias)
//   A [M,K] K-major, B [N,K] K-major. CTA tile 128x256, 8 warps (64x64 each),
//   BK=64, 2-stage cp.async pipeline, hoisted LDSM, pass-major MMA order.
// ===========================================================================
#define BK      64
#define APITCH  72
#define TILEA   (128*APITCH*2)
#define TILEBB  (256*APITCH*2)
#define STGB    (2*TILEA + 2*TILEBB)
#define NSTG    2
#define GEMM_SMEM (NSTG*STGB)      // 221184

#define OFF_AHI 0
#define OFF_ALO (TILEA)
#define OFF_BHI (2*TILEA)
#define OFF_BLO (2*TILEA + TILEBB)

__global__ void __launch_bounds__(256, 1) tgemm(GP p)
{
    const int m0 = blockIdx.y * 128;
    const int n0 = blockIdx.x * 256;
    if (p.maskSkip && (n0 + 256 <= m0)) return;

    extern __shared__ char smem[];
    const uint32_t sbase = smem_u32(smem);

    const int tid  = threadIdx.x;
    const int wid  = tid >> 5;
    const int lane = tid & 31;
    const int g    = lane >> 2;
    const int tg   = lane & 3;
    const int wm0 = (wid & 1) * 64;
    const int wn0 = (wid >> 1) * 64;

    const size_t zA = (size_t)blockIdx.z * p.szA;
    const size_t zB = (size_t)blockIdx.z * p.szB;
    const size_t zC = (size_t)blockIdx.z * p.szC;

    const char* aHi = (const char*)(p.Ahi + zA + (size_t)m0 * p.ldA);
    const char* aLo = (const char*)(p.Alo + zA + (size_t)m0 * p.ldA);
    const char* bHi = (const char*)(p.Bhi + zB + (size_t)n0 * p.ldB);
    const char* bLo = (const char*)(p.Blo + zB + (size_t)n0 * p.ldB);
    const size_t rsA = (size_t)p.ldA * 2;
    const size_t rsB = (size_t)p.ldB * 2;

    const int l15 = lane & 15;
    const uint32_t aoff = (uint32_t)(((wm0 + l15) * APITCH + ((lane >> 4) * 8)) * 2);
    const int bN  = ((lane & 16) >> 1) + (lane & 7);
    const uint32_t boff = (uint32_t)(((wn0 + bN) * APITCH + (lane & 8)) * 2);

    const int r0c = tid >> 3;
    const int ccc = (tid & 7) * 16;

    const int NC = p.K / BK;
    const int c0 = p.triK ? (m0 / BK) : 0;
    const int NCr = NC - c0;

    auto load_chunk = [&](int c, int stg) {
        const size_t kb = (size_t)c * BK * 2;
        const uint32_t sb = sbase + stg * STGB;
        #pragma unroll
        for (int h = 0; h < 4; h++) {
            const int row = r0c + h * 32;
            const uint32_t doff = row * (APITCH*2) + ccc;
            const size_t goA = (size_t)row * rsA + kb + ccc;
            CP_ASYNC16(sb + OFF_AHI + doff, aHi + goA);
            CP_ASYNC16(sb + OFF_ALO + doff, aLo + goA);
        }
        #pragma unroll
        for (int h = 0; h < 8; h++) {
            const int row = r0c + h * 32;
            const uint32_t doff = row * (APITCH*2) + ccc;
            const size_t goB = (size_t)row * rsB + kb + ccc;
            CP_ASYNC16(sb + OFF_BHI + doff, bHi + goB);
            CP_ASYNC16(sb + OFF_BLO + doff, bLo + goB);
        }
        CP_COMMIT();
    };

    float acc[4][8][4];
    #pragma unroll
    for (int a = 0; a < 4; a++)
        #pragma unroll
        for (int b = 0; b < 8; b++)
            #pragma unroll
            for (int q = 0; q < 4; q++) acc[a][b][q] = 0.f;

    load_chunk(c0 + 0, 0);
    load_chunk(c0 + 1, 1);

    for (int cr = 0; cr < NCr; cr++) {
        const int stg = cr & 1;
        if (cr + 1 < NCr) CP_WAIT(1);
        else              CP_WAIT(0);
        __syncthreads();

        const uint32_t sb = sbase + stg * STGB;
        #pragma unroll
        for (int kk = 0; kk < BK; kk += 16) {
            uint32_t ah[4][4], al[4][4], bh[4][4], bl[4][4];
            // hoist ALL fragment loads for this k-step
            #pragma unroll
            for (int mt = 0; mt < 4; mt++) {
                const uint32_t ao = sb + aoff + mt*(16*APITCH*2) + kk*2;
                LDSM4(ah[mt], ao);
                LDSM4(al[mt], ao + TILEA);
            }
            #pragma unroll
            for (int ntp = 0; ntp < 4; ntp++) {
                const uint32_t bo = sb + OFF_BHI + boff + ntp*(16*APITCH*2) + kk*2;
                LDSM4(bh[ntp], bo);
                LDSM4(bl[ntp], bo + TILEBB);
            }
            // 3 pass-major blocks of 32 independent MMAs
            #pragma unroll
            for (int mt = 0; mt < 4; mt++)
                #pragma unroll
                for (int nt = 0; nt < 8; nt++)
                    mma16816(acc[mt][nt], ah[mt], &bh[nt >> 1][(nt & 1) * 2]);
            #pragma unroll
            for (int mt = 0; mt < 4; mt++)
                #pragma unroll
                for (int nt = 0; nt < 8; nt++)
                    mma16816(acc[mt][nt], ah[mt], &bl[nt >> 1][(nt & 1) * 2]);
            #pragma unroll
            for (int mt = 0; mt < 4; mt++)
                #pragma unroll
                for (int nt = 0; nt < 8; nt++)
                    mma16816(acc[mt][nt], al[mt], &bh[nt >> 1][(nt & 1) * 2]);
        }

        __syncthreads();
        if (cr + NSTG < NCr) load_chunk(c0 + cr + NSTG, stg);
    }

    // ---- epilogue ----
    float2 bb[8];
    #pragma unroll
    for (int nt = 0; nt < 8; nt++) {
        if (p.bias) bb[nt] = *(const float2*)(p.bias + n0 + wn0 + nt*8 + tg*2);
        else        bb[nt] = make_float2(0.f, 0.f);
    }
    #pragma unroll
    for (int mt = 0; mt < 4; mt++) {
        #pragma unroll
        for (int half = 0; half < 2; half++) {
            const int r = m0 + wm0 + mt*16 + g + half*8;
            #pragma unroll
            for (int nt = 0; nt < 8; nt++) {
                float x0 = acc[mt][nt][half*2+0] * p.scale + bb[nt].x;
                float x1 = acc[mt][nt][half*2+1] * p.scale + bb[nt].y;
                if (p.relu) { x0 = fmaxf(x0, 0.f); x1 = fmaxf(x1, 0.f); }
                const size_t o = zC + (size_t)r * p.ldC + n0 + wn0 + nt*8 + tg*2;
                if (p.outF)
                    *(float2*)(p.outF + o) = make_float2(x0, x1);
                if (p.outHi) {
                    uint32_t hp, lp;
                    split_pack(x0, x1, hp, lp);
                    *(uint32_t*)(p.outHi + o) = hp;
                    *(uint32_t*)(p.outLo + o) = lp;
                }
            }
        }
    }
}

// ---------------------------------------------------------------------------
// Embedding gather + hi/lo split
// ---------------------------------------------------------------------------
__global__ void embed_split(const int* __restrict__ x, const float* __restrict__ emb,
                            __nv_bfloat16* __restrict__ hhi, __nv_bfloat16* __restrict__ hlo)
{
    const int r = blockIdx.x;
    const int row = x[r];
    const float4 f = ((const float4*)(emb + (size_t)row * EDIM))[threadIdx.x];
    const size_t o = (size_t)r * EDIM + threadIdx.x * 4;
    uint32_t hp, lp;
    split_pack(f.x, f.y, hp, lp);
    *(uint32_t*)(hhi + o)     = hp;  *(uint32_t*)(hlo + o)     = lp;
    split_pack(f.z, f.w, hp, lp);
    *(uint32_t*)(hhi + o + 2) = hp;  *(uint32_t*)(hlo + o + 2) = lp;
}

// ---------------------------------------------------------------------------
// Weight transpose + hi/lo split: fp32 [R,C] -> bf16 [C,R]
// ---------------------------------------------------------------------------
__global__ void transpose_split(const float* __restrict__ src,
                                __nv_bfloat16* __restrict__ dhi,
                                __nv_bfloat16* __restrict__ dlo,
                                int R, int C, size_t szSrc, size_t szDst)
{
    __shared__ float t[32][33];
    src += (size_t)blockIdx.z * szSrc;
    dhi += (size_t)blockIdx.z * szDst;
    dlo += (size_t)blockIdx.z * szDst;
    const int c0 = blockIdx.x * 32, r0 = blockIdx.y * 32;
    const int tx = threadIdx.x, ty = threadIdx.y;
    #pragma unroll
    for (int j = 0; j < 4; j++)
        t[ty + j*8][tx] = src[(size_t)(r0 + ty + j*8) * C + c0 + tx];
    __syncthreads();
    #pragma unroll
    for (int j = 0; j < 4; j++) {
        const float v = t[tx][ty + j*8];
        __nv_bfloat16 h, l;
        split2(v, h, l);
        const size_t o = (size_t)(c0 + ty + j*8) * R + r0 + tx;
        dhi[o] = h; dlo[o] = l;
    }
}

// ---------------------------------------------------------------------------
// V transpose from fused QKV buffer (bf16 hi/lo): [S, cols@2048..3071] -> [E,S]
// ---------------------------------------------------------------------------
__global__ void transpose_v(const uint16_t* __restrict__ qkvhi,
                            const uint16_t* __restrict__ qkvlo,
                            uint16_t* __restrict__ dhi, uint16_t* __restrict__ dlo)
{
    __shared__ uint32_t t[32][33];
    const int b = blockIdx.z;
    const int c0 = blockIdx.x * 32;
    const int r0 = blockIdx.y * 32;
    const int tx = threadIdx.x, ty = threadIdx.y;
    const size_t srcBase = (size_t)b * SEQ * (3*EDIM) + 2048;
    #pragma unroll
    for (int j = 0; j < 4; j++) {
        const size_t idx = srcBase + (size_t)(r0 + ty + j*8) * (3*EDIM) + c0 + tx;
        t[ty + j*8][tx] = (uint32_t)qkvhi[idx] | ((uint32_t)qkvlo[idx] << 16);
    }
    __syncthreads();
    const size_t dstBase = (size_t)b * EDIM * SEQ;
    #pragma unroll
    for (int j = 0; j < 4; j++) {
        const uint32_t v = t[tx][ty + j*8];
        const size_t o = dstBase + (size_t)(c0 + ty + j*8) * SEQ + r0 + tx;
        dhi[o] = (uint16_t)(v & 0xFFFF);
        dlo[o] = (uint16_t)(v >> 16);
    }
}

// ---------------------------------------------------------------------------
// Masked softmax (keep t >= s), fp32 in -> bf16 hi/lo out, register-cached
// ---------------------------------------------------------------------------
__global__ void __launch_bounds__(256) softmax_split(const float* __restrict__ sc,
                                                     __nv_bfloat16* __restrict__ whi,
                                                     __nv_bfloat16* __restrict__ wlo)
{
    const int s = blockIdx.x, b = blockIdx.y;
    const size_t base = ((size_t)b * SEQ + s) * SEQ;
    const float* row = sc + base;
    const int tid = threadIdx.x;
    __shared__ float red[256];

    float rv[8];
    float m = -1e30f;
    {
        int j = 0;
        for (int t = s + tid; t < SEQ; t += 256, j++) {
            rv[j] = row[t];
            m = fmaxf(m, rv[j]);
        }
    }
    red[tid] = m; __syncthreads();
    #pragma unroll
    for (int o = 128; o > 0; o >>= 1) {
        if (tid < o) red[tid] = fmaxf(red[tid], red[tid + o]);
        __syncthreads();
    }
    m = red[0]; __syncthreads();

    float ev[8];
    float sum = 0.f;
    {
        int j = 0;
        for (int t = s + tid; t < SEQ; t += 256, j++) {
            const float e = expf(rv[j] - m);
            ev[j] = e;
            sum += e;
        }
    }
    red[tid] = sum; __syncthreads();
    #pragma unroll
    for (int o = 128; o > 0; o >>= 1) {
        if (tid < o) red[tid] += red[tid + o];
        __syncthreads();
    }
    const float inv = 1.f / red[0];

    for (int t = tid; t < s; t += 256) {
        whi[base + t] = __float2bfloat16(0.f);
        wlo[base + t] = __float2bfloat16(0.f);
    }
    {
        int j = 0;
        for (int t = s + tid; t < SEQ; t += 256, j++) {
            __nv_bfloat16 h, l;
            split2(ev[j] * inv, h, l);
            whi[base + t] = h;
            wlo[base + t] = l;
        }
    }
}

// ---------------------------------------------------------------------------
// Host
// ---------------------------------------------------------------------------
template <typename T>
static T* sym(const void* s) { void* p = nullptr; cudaGetSymbolAddress(&p, s); return (T*)p; }

extern "C" void kernel_launch(void* const* d_in, const int* in_sizes, int n_in,
                              void* d_out, int out_size)
{
    const int*   x   = (const int*)  d_in[0];
    const float* emb = (const float*)d_in[1];
    const float* Wq  = (const float*)d_in[2];
    const float* bq  = (const float*)d_in[3];
    const float* Wk  = (const float*)d_in[4];
    const float* bk  = (const float*)d_in[5];
    const float* Wv  = (const float*)d_in[6];
    const float* bv  = (const float*)d_in[7];
    const float* W1  = (const float*)d_in[8];
    const float* b1  = (const float*)d_in[9];
    const float* W2  = (const float*)d_in[10];
    const float* b2  = (const float*)d_in[11];
    float* out = (float*)d_out;

    static int once = 0;
    if (!once) {
        once = 1;
        cudaFuncSetAttribute(tgemm, cudaFuncAttributeMaxDynamicSharedMemorySize, GEMM_SMEM);
    }

    __nv_bfloat16* hhi  = sym<__nv_bfloat16>(g_hhi);
    __nv_bfloat16* hlo  = sym<__nv_bfloat16>(g_hlo);
    __nv_bfloat16* phi  = sym<__nv_bfloat16>(g_phi);
    __nv_bfloat16* plo  = sym<__nv_bfloat16>(g_plo);
    __nv_bfloat16* qkvhi= sym<__nv_bfloat16>(g_qkvhi);
    __nv_bfloat16* qkvlo= sym<__nv_bfloat16>(g_qkvlo);
    __nv_bfloat16* vthi = sym<__nv_bfloat16>(g_vthi);
    __nv_bfloat16* vtlo = sym<__nv_bfloat16>(g_vtlo);
    float*         sc   = sym<float>(g_sc);
    __nv_bfloat16* whi  = sym<__nv_bfloat16>(g_whi);
    __nv_bfloat16* wlo  = sym<__nv_bfloat16>(g_wlo);
    __nv_bfloat16* mhi  = sym<__nv_bfloat16>(g_mhi);
    __nv_bfloat16* mlo  = sym<__nv_bfloat16>(g_mlo);
    __nv_bfloat16* wqkvt= sym<__nv_bfloat16>(g_wqkvt);
    __nv_bfloat16* w1t  = sym<__nv_bfloat16>(g_w1t);
    __nv_bfloat16* w2t  = sym<__nv_bfloat16>(g_w2t);
    float*         bqkv = sym<float>(g_bqkv);

    const size_t EE = (size_t)EDIM * EDIM;
    const size_t EM = (size_t)EDIM * MDIM;
    __nv_bfloat16* wqkvtHi = wqkvt;
    __nv_bfloat16* wqkvtLo = wqkvt + 3*EE;

    cudaMemcpyAsync(bqkv,            bq, EDIM*sizeof(float), cudaMemcpyDeviceToDevice);
    cudaMemcpyAsync(bqkv + EDIM,     bk, EDIM*sizeof(float), cudaMemcpyDeviceToDevice);
    cudaMemcpyAsync(bqkv + 2*EDIM,   bv, EDIM*sizeof(float), cudaMemcpyDeviceToDevice);

    dim3 tb(32, 8);
    // kernels 1-5, QKV GEMM = kernel 6 (ncu -s 5 -c 1 target)
    transpose_split<<<dim3(EDIM/32, EDIM/32, 1), tb>>>(Wq, wqkvtHi + 0*EE, wqkvtLo + 0*EE, EDIM, EDIM, 0, 0);
    transpose_split<<<dim3(EDIM/32, EDIM/32, 1), tb>>>(Wk, wqkvtHi + 1*EE, wqkvtLo + 1*EE, EDIM, EDIM, 0, 0);
    transpose_split<<<dim3(EDIM/32, EDIM/32, 1), tb>>>(Wv, wqkvtHi + 2*EE, wqkvtLo + 2*EE, EDIM, EDIM, 0, 0);
    embed_split<<<NROWS, 256>>>(x, emb, hhi, hlo);
    transpose_split<<<dim3(MDIM/32, EDIM/32, NLAY), tb>>>(W1, w1t, w1t + (size_t)NLAY*EM, EDIM, MDIM, EM, EM);

    GP p = {};

    // ---- fused QKV: [8192,1024] x [3072,1024]^T ----
    p.Ahi = hhi; p.Alo = hlo; p.Bhi = wqkvtHi; p.Blo = wqkvtLo;
    p.bias = bqkv; p.outHi = qkvhi; p.outLo = qkvlo; p.outF = nullptr;
    p.K = EDIM; p.ldA = EDIM; p.ldB = EDIM; p.ldC = 3*EDIM;
    p.scale = 1.f; p.relu = 0; p.maskSkip = 0; p.triK = 0;
    p.szA = p.szB = p.szC = 0;
    tgemm<<<dim3((3*EDIM)/256, NROWS/128, 1), 256, GEMM_SMEM>>>(p);

    transpose_split<<<dim3(EDIM/32, MDIM/32, NLAY), tb>>>(W2, w2t, w2t + (size_t)NLAY*EM, MDIM, EDIM, EM, EM);
    transpose_v<<<dim3(EDIM/32, SEQ/32, BATCH), tb>>>((const uint16_t*)qkvhi, (const uint16_t*)qkvlo,
                                                      (uint16_t*)vthi, (uint16_t*)vtlo);

    // ---- scores = scale * q k^T ----
    p.Ahi = qkvhi;        p.Alo = qkvlo;
    p.Bhi = qkvhi + EDIM; p.Blo = qkvlo + EDIM;
    p.ldA = 3*EDIM; p.ldB = 3*EDIM; p.ldC = SEQ; p.K = EDIM;
    p.szA = (size_t)SEQ * 3*EDIM; p.szB = (size_t)SEQ * 3*EDIM; p.szC = (size_t)SEQ * SEQ;
    p.bias = nullptr; p.outF = sc; p.outHi = nullptr; p.outLo = nullptr;
    p.scale = 1.f / 32.f; p.relu = 0; p.maskSkip = 1; p.triK = 0;
    tgemm<<<dim3(SEQ/256, SEQ/128, BATCH), 256, GEMM_SMEM>>>(p);

    softmax_split<<<dim3(SEQ, BATCH), 256>>>(sc, whi, wlo);

    // ---- h = relu(w v) ----
    p.Ahi = whi; p.Alo = wlo; p.Bhi = vthi; p.Blo = vtlo;
    p.ldA = SEQ; p.ldB = SEQ; p.ldC = EDIM; p.K = SEQ;
    p.szA = (size_t)SEQ * SEQ; p.szB = (size_t)EDIM * SEQ; p.szC = (size_t)SEQ * EDIM;
    p.bias = nullptr; p.outF = nullptr; p.outHi = hhi; p.outLo = hlo;
    p.scale = 1.f; p.relu = 1; p.maskSkip = 0; p.triK = 1;
    tgemm<<<dim3(EDIM/256, SEQ/128, BATCH), 256, GEMM_SMEM>>>(p);

    // ---- MLP stack ----
    p.szA = p.szB = p.szC = 0;
    p.maskSkip = 0; p.triK = 0;
    __nv_bfloat16 *curHi = hhi, *curLo = hlo;
    __nv_bfloat16 *altHi = phi, *altLo = plo;
    for (int i = 0; i < NLAY; i++) {
        p.Ahi = curHi; p.Alo = curLo;
        p.Bhi = w1t + (size_t)i * EM; p.Blo = w1t + (size_t)(NLAY + i) * EM;
        p.ldA = EDIM; p.ldB = EDIM; p.ldC = MDIM; p.K = EDIM;
        p.bias = b1 + (size_t)i * MDIM;
        p.outHi = mhi; p.outLo = mlo; p.outF = nullptr;
        p.scale = 1.f; p.relu = 1;
        tgemm<<<dim3(MDIM/256, NROWS/128, 1), 256, GEMM_SMEM>>>(p);

        p.Ahi = mhi; p.Alo = mlo;
        p.Bhi = w2t + (size_t)i * EM; p.Blo = w2t + (size_t)(NLAY + i) * EM;
        p.ldA = MDIM; p.ldB = MDIM; p.ldC = EDIM; p.K = MDIM;
        p.bias = b2 + (size_t)i * EDIM;
        if (i == NLAY - 1) { p.outHi = nullptr; p.outLo = nullptr; p.outF = out; }
        else               { p.outHi = altHi;  p.outLo = altLo;  p.outF = nullptr; }
        tgemm<<<dim3(EDIM/256, NROWS/128, 1), 256, GEMM_SMEM>>>(p);

        __nv_bfloat16* t;
        t = curHi; curHi = altHi; altHi = t;
        t = curLo; curLo = altLo; altLo = t;
    }
}

// round 11
// speedup vs baseline: 1.1216x; 1.0128x over previous
#include <cuda_runtime.h>
#include <cuda_bf16.h>
#include <math.h>
#include <stdint.h>

// ---------------------------------------------------------------------------
// Problem constants
// ---------------------------------------------------------------------------
#define VOCAB 32000
#define EDIM  1024
#define MDIM  4096
#define NLAY  4
#define BATCH 4
#define SEQ   2048
#define NROWS (BATCH*SEQ)   // 8192

// ---------------------------------------------------------------------------
// Static device scratch
// ---------------------------------------------------------------------------
__device__ __nv_bfloat16 g_hhi [NROWS * EDIM];
__device__ __nv_bfloat16 g_hlo [NROWS * EDIM];
__device__ __nv_bfloat16 g_qhi [NROWS * EDIM];
__device__ __nv_bfloat16 g_qlo [NROWS * EDIM];
__device__ __nv_bfloat16 g_khi [NROWS * EDIM];
__device__ __nv_bfloat16 g_klo [NROWS * EDIM];
__device__ float         g_v   [NROWS * EDIM];
__device__ __nv_bfloat16 g_vthi[(size_t)BATCH * EDIM * SEQ];
__device__ __nv_bfloat16 g_vtlo[(size_t)BATCH * EDIM * SEQ];
__device__ float         g_sc  [(size_t)BATCH * SEQ * SEQ];
__device__ __nv_bfloat16 g_whi [(size_t)BATCH * SEQ * SEQ];
__device__ __nv_bfloat16 g_wlo [(size_t)BATCH * SEQ * SEQ];
__device__ __nv_bfloat16 g_mhi [(size_t)NROWS * MDIM];
__device__ __nv_bfloat16 g_mlo [(size_t)NROWS * MDIM];
__device__ __nv_bfloat16 g_wqt [2 * EDIM * EDIM];
__device__ __nv_bfloat16 g_wkt [2 * EDIM * EDIM];
__device__ __nv_bfloat16 g_wvt [2 * EDIM * EDIM];
__device__ __nv_bfloat16 g_w1t [(size_t)2 * NLAY * MDIM * EDIM];
__device__ __nv_bfloat16 g_w2t [(size_t)2 * NLAY * EDIM * MDIM];

// ---------------------------------------------------------------------------
// PTX helpers (valid at plain compute_103 target)
// ---------------------------------------------------------------------------
#define CP_ASYNC16(dst, src) \
    asm volatile("cp.async.cg.shared.global [%0], [%1], 16;" :: "r"(dst), "l"(src))
#define CP_COMMIT() asm volatile("cp.async.commit_group;" ::: "memory")
#define CP_WAIT(n)  asm volatile("cp.async.wait_group %0;" :: "n"(n) : "memory")

__device__ __forceinline__ uint32_t smem_u32(const void* p) {
    uint32_t a;
    asm("{ .reg .u64 t; cvta.to.shared.u64 t, %1; cvt.u32.u64 %0, t; }"
        : "=r"(a) : "l"(p));
    return a;
}

#define LDSM4(R, A) \
    asm volatile("ldmatrix.sync.aligned.m8n8.x4.shared.b16 {%0,%1,%2,%3}, [%4];" \
        : "=r"((R)[0]), "=r"((R)[1]), "=r"((R)[2]), "=r"((R)[3]) : "r"(A))

__device__ __forceinline__ void mma16816(float* c, const uint32_t* a, const uint32_t* b) {
    asm volatile(
        "mma.sync.aligned.m16n8k16.row.col.f32.bf16.bf16.f32 "
        "{%0,%1,%2,%3}, {%4,%5,%6,%7}, {%8,%9}, {%0,%1,%2,%3};"
        : "+f"(c[0]), "+f"(c[1]), "+f"(c[2]), "+f"(c[3])
        : "r"(a[0]), "r"(a[1]), "r"(a[2]), "r"(a[3]), "r"(b[0]), "r"(b[1]));
}

__device__ __forceinline__ void split2(float v, __nv_bfloat16& hi, __nv_bfloat16& lo) {
    hi = __float2bfloat16(v);
    lo = __float2bfloat16(v - __bfloat162float(hi));
}

// ---------------------------------------------------------------------------
// HMMA GEMM (round-6 champion): out = act(scale*(Ahi+Alo)(Bhi+Blo)^T + bias)
//   A [M,K] K-major, B [N,K] K-major. CTA tile 128x256, 8 warps (64x64 each),
//   BK=64, 2-stage cp.async pipeline, interleaved LDSM, pass-major MMA order.
// ---------------------------------------------------------------------------
struct GP {
    const __nv_bfloat16 *Ahi, *Alo, *Bhi, *Blo;
    const float* bias;
    float* outF;
    __nv_bfloat16 *outHi, *outLo;
    int K, ldA, ldB, ldC;
    size_t szA, szB, szC;
    float scale;
    int relu;
    int maskSkip;
    int triK;
};

#define BK      64
#define APITCH  72
#define TILEA   (128*APITCH*2)
#define TILEBB  (256*APITCH*2)
#define STGB    (2*TILEA + 2*TILEBB)
#define NSTG    2
#define GEMM_SMEM (NSTG*STGB)      // 221184

#define OFF_AHI 0
#define OFF_ALO (TILEA)
#define OFF_BHI (2*TILEA)
#define OFF_BLO (2*TILEA + TILEBB)

__global__ void __launch_bounds__(256, 1) tgemm(GP p)
{
    const int m0 = blockIdx.y * 128;
    const int n0 = blockIdx.x * 256;
    if (p.maskSkip && (n0 + 256 <= m0)) return;

    extern __shared__ char smem[];
    const uint32_t sbase = smem_u32(smem);

    const int tid  = threadIdx.x;
    const int wid  = tid >> 5;
    const int lane = tid & 31;
    const int g    = lane >> 2;
    const int tg   = lane & 3;
    const int wm0 = (wid & 1) * 64;
    const int wn0 = (wid >> 1) * 64;

    const size_t zA = (size_t)blockIdx.z * p.szA;
    const size_t zB = (size_t)blockIdx.z * p.szB;
    const size_t zC = (size_t)blockIdx.z * p.szC;

    const char* aHi = (const char*)(p.Ahi + zA + (size_t)m0 * p.ldA);
    const char* aLo = (const char*)(p.Alo + zA + (size_t)m0 * p.ldA);
    const char* bHi = (const char*)(p.Bhi + zB + (size_t)n0 * p.ldB);
    const char* bLo = (const char*)(p.Blo + zB + (size_t)n0 * p.ldB);
    const size_t rsA = (size_t)p.ldA * 2;
    const size_t rsB = (size_t)p.ldB * 2;

    const int l15 = lane & 15;
    const uint32_t aoff = (uint32_t)(((wm0 + l15) * APITCH + ((lane >> 4) * 8)) * 2);
    const int bN  = ((lane & 16) >> 1) + (lane & 7);
    const uint32_t boff = (uint32_t)(((wn0 + bN) * APITCH + (lane & 8)) * 2);

    const int r0c = tid >> 3;
    const int ccc = (tid & 7) * 16;

    const int NC = p.K / BK;
    const int c0 = p.triK ? (m0 / BK) : 0;
    const int NCr = NC - c0;

    auto load_chunk = [&](int c, int stg) {
        const size_t kb = (size_t)c * BK * 2;
        const uint32_t sb = sbase + stg * STGB;
        #pragma unroll
        for (int h = 0; h < 4; h++) {
            const int row = r0c + h * 32;
            const uint32_t doff = row * (APITCH*2) + ccc;
            const size_t goA = (size_t)row * rsA + kb + ccc;
            CP_ASYNC16(sb + OFF_AHI + doff, aHi + goA);
            CP_ASYNC16(sb + OFF_ALO + doff, aLo + goA);
        }
        #pragma unroll
        for (int h = 0; h < 8; h++) {
            const int row = r0c + h * 32;
            const uint32_t doff = row * (APITCH*2) + ccc;
            const size_t goB = (size_t)row * rsB + kb + ccc;
            CP_ASYNC16(sb + OFF_BHI + doff, bHi + goB);
            CP_ASYNC16(sb + OFF_BLO + doff, bLo + goB);
        }
        CP_COMMIT();
    };

    float acc[4][8][4];
    #pragma unroll
    for (int a = 0; a < 4; a++)
        #pragma unroll
        for (int b = 0; b < 8; b++)
            #pragma unroll
            for (int q = 0; q < 4; q++) acc[a][b][q] = 0.f;

    load_chunk(c0 + 0, 0);
    load_chunk(c0 + 1, 1);

    for (int cr = 0; cr < NCr; cr++) {
        const int stg = cr & 1;
        if (cr + 1 < NCr) CP_WAIT(1);
        else              CP_WAIT(0);
        __syncthreads();

        const uint32_t sb = sbase + stg * STGB;
        #pragma unroll
        for (int kk = 0; kk < BK; kk += 16) {
            uint32_t ah[4][4], al[4][4];
            #pragma unroll
            for (int mt = 0; mt < 4; mt++) {
                const uint32_t ao = sb + aoff + mt*(16*APITCH*2) + kk*2;
                LDSM4(ah[mt], ao);
                LDSM4(al[mt], ao + TILEA);
            }
            #pragma unroll
            for (int ntp = 0; ntp < 4; ntp++) {
                uint32_t bh[4], bl[4];
                const uint32_t bo = sb + OFF_BHI + boff + ntp*(16*APITCH*2) + kk*2;
                LDSM4(bh, bo);
                LDSM4(bl, bo + TILEBB);
                #pragma unroll
                for (int mt = 0; mt < 4; mt++)
                    #pragma unroll
                    for (int nt = 0; nt < 2; nt++)
                        mma16816(acc[mt][ntp*2+nt], ah[mt], &bh[nt*2]);
                #pragma unroll
                for (int mt = 0; mt < 4; mt++)
                    #pragma unroll
                    for (int nt = 0; nt < 2; nt++)
                        mma16816(acc[mt][ntp*2+nt], ah[mt], &bl[nt*2]);
                #pragma unroll
                for (int mt = 0; mt < 4; mt++)
                    #pragma unroll
                    for (int nt = 0; nt < 2; nt++)
                        mma16816(acc[mt][ntp*2+nt], al[mt], &bh[nt*2]);
            }
        }

        __syncthreads();
        if (cr + NSTG < NCr) load_chunk(c0 + cr + NSTG, stg);
    }

    float2 bb[8];
    #pragma unroll
    for (int nt = 0; nt < 8; nt++) {
        if (p.bias) bb[nt] = *(const float2*)(p.bias + n0 + wn0 + nt*8 + tg*2);
        else        bb[nt] = make_float2(0.f, 0.f);
    }
    #pragma unroll
    for (int mt = 0; mt < 4; mt++) {
        #pragma unroll
        for (int half = 0; half < 2; half++) {
            const int r = m0 + wm0 + mt*16 + g + half*8;
            #pragma unroll
            for (int nt = 0; nt < 8; nt++) {
                float x0 = acc[mt][nt][half*2+0] * p.scale + bb[nt].x;
                float x1 = acc[mt][nt][half*2+1] * p.scale + bb[nt].y;
                if (p.relu) { x0 = fmaxf(x0, 0.f); x1 = fmaxf(x1, 0.f); }
                const int cc = n0 + wn0 + nt*8 + tg*2;
                const size_t o = zC + (size_t)r * p.ldC + cc;
                if (p.outF)
                    *(float2*)(p.outF + o) = make_float2(x0, x1);
                if (p.outHi) {
                    __nv_bfloat16 h0, l0, h1, l1;
                    split2(x0, h0, l0);
                    split2(x1, h1, l1);
                    uint32_t hp = (uint32_t)__bfloat16_as_ushort(h0) |
                                  ((uint32_t)__bfloat16_as_ushort(h1) << 16);
                    uint32_t lp = (uint32_t)__bfloat16_as_ushort(l0) |
                                  ((uint32_t)__bfloat16_as_ushort(l1) << 16);
                    *(uint32_t*)(p.outHi + o) = hp;
                    *(uint32_t*)(p.outLo + o) = lp;
                }
            }
        }
    }
}

// ---------------------------------------------------------------------------
// Embedding gather + hi/lo split
// ---------------------------------------------------------------------------
__global__ void embed_split(const int* __restrict__ x, const float* __restrict__ emb,
                            __nv_bfloat16* __restrict__ hhi, __nv_bfloat16* __restrict__ hlo)
{
    const int r = blockIdx.x;
    const int row = x[r];
    const float4 f = ((const float4*)(emb + (size_t)row * EDIM))[threadIdx.x];
    const size_t o = (size_t)r * EDIM + threadIdx.x * 4;
    __nv_bfloat16 h, l;
    split2(f.x, h, l); hhi[o+0] = h; hlo[o+0] = l;
    split2(f.y, h, l); hhi[o+1] = h; hlo[o+1] = l;
    split2(f.z, h, l); hhi[o+2] = h; hlo[o+2] = l;
    split2(f.w, h, l); hhi[o+3] = h; hlo[o+3] = l;
}

// ---------------------------------------------------------------------------
// Transpose + hi/lo split: src fp32 [R,C] -> dst bf16 [C,R] (hi,lo)
// ---------------------------------------------------------------------------
__global__ void transpose_split(const float* __restrict__ src,
                                __nv_bfloat16* __restrict__ dhi,
                                __nv_bfloat16* __restrict__ dlo,
                                int R, int C, size_t szSrc, size_t szDst)
{
    __shared__ float t[32][33];
    src += (size_t)blockIdx.z * szSrc;
    dhi += (size_t)blockIdx.z * szDst;
    dlo += (size_t)blockIdx.z * szDst;
    const int c0 = blockIdx.x * 32, r0 = blockIdx.y * 32;
    const int tx = threadIdx.x, ty = threadIdx.y;
    #pragma unroll
    for (int j = 0; j < 4; j++)
        t[ty + j*8][tx] = src[(size_t)(r0 + ty + j*8) * C + c0 + tx];
    __syncthreads();
    #pragma unroll
    for (int j = 0; j < 4; j++) {
        const float v = t[tx][ty + j*8];
        __nv_bfloat16 h, l;
        split2(v, h, l);
        const size_t o = (size_t)(c0 + ty + j*8) * R + r0 + tx;
        dhi[o] = h; dlo[o] = l;
    }
}

// ---------------------------------------------------------------------------
// Masked softmax (keep t >= s), fp32 in -> bf16 hi/lo out, exp cached in regs
// ---------------------------------------------------------------------------
__global__ void __launch_bounds__(256) softmax_split(const float* __restrict__ sc,
                                                     __nv_bfloat16* __restrict__ whi,
                                                     __nv_bfloat16* __restrict__ wlo)
{
    const int s = blockIdx.x, b = blockIdx.y;
    const size_t base = ((size_t)b * SEQ + s) * SEQ;
    const float* row = sc + base;
    const int tid = threadIdx.x;
    __shared__ float red[256];

    float m = -1e30f;
    for (int t = s + tid; t < SEQ; t += 256) m = fmaxf(m, row[t]);
    red[tid] = m; __syncthreads();
    #pragma unroll
    for (int o = 128; o > 0; o >>= 1) {
        if (tid < o) red[tid] = fmaxf(red[tid], red[tid + o]);
        __syncthreads();
    }
    m = red[0]; __syncthreads();

    float ev[8];
    float sum = 0.f;
    {
        int j = 0;
        for (int t = s + tid; t < SEQ; t += 256, j++) {
            const float e = expf(row[t] - m);
            ev[j] = e;
            sum += e;
        }
    }
    red[tid] = sum; __syncthreads();
    #pragma unroll
    for (int o = 128; o > 0; o >>= 1) {
        if (tid < o) red[tid] += red[tid + o];
        __syncthreads();
    }
    const float inv = 1.f / red[0];

    for (int t = tid; t < s; t += 256) {
        whi[base + t] = __float2bfloat16(0.f);
        wlo[base + t] = __float2bfloat16(0.f);
    }
    {
        int j = 0;
        for (int t = s + tid; t < SEQ; t += 256, j++) {
            __nv_bfloat16 h, l;
            split2(ev[j] * inv, h, l);
            whi[base + t] = h;
            wlo[base + t] = l;
        }
    }
}

// ---------------------------------------------------------------------------
// Host
// ---------------------------------------------------------------------------
template <typename T>
static T* sym(const void* s) { void* p = nullptr; cudaGetSymbolAddress(&p, s); return (T*)p; }

static void launch_gemm(GP& p, int M, int N, int Z, cudaStream_t st)
{
    dim3 g(N / 256, M / 128, Z);
    tgemm<<<g, 256, GEMM_SMEM, st>>>(p);
}

extern "C" void kernel_launch(void* const* d_in, const int* in_sizes, int n_in,
                              void* d_out, int out_size)
{
    const int*   x   = (const int*)  d_in[0];
    const float* emb = (const float*)d_in[1];
    const float* Wq  = (const float*)d_in[2];
    const float* bq  = (const float*)d_in[3];
    const float* Wk  = (const float*)d_in[4];
    const float* bk  = (const float*)d_in[5];
    const float* Wv  = (const float*)d_in[6];
    const float* bv  = (const float*)d_in[7];
    const float* W1  = (const float*)d_in[8];
    const float* b1  = (const float*)d_in[9];
    const float* W2  = (const float*)d_in[10];
    const float* b2  = (const float*)d_in[11];
    float* out = (float*)d_out;

    // one-time resources (created on the uncaptured correctness call)
    static cudaStream_t s1 = nullptr, s2 = nullptr;
    static cudaEvent_t ev0 = nullptr, evW = nullptr, evV = nullptr, evVT = nullptr;
    if (!s1) {
        cudaFuncSetAttribute(tgemm, cudaFuncAttributeMaxDynamicSharedMemorySize, GEMM_SMEM);
        cudaStreamCreateWithFlags(&s1, cudaStreamNonBlocking);
        cudaStreamCreateWithFlags(&s2, cudaStreamNonBlocking);
        cudaEventCreateWithFlags(&ev0, cudaEventDisableTiming);
        cudaEventCreateWithFlags(&evW, cudaEventDisableTiming);
        cudaEventCreateWithFlags(&evV, cudaEventDisableTiming);
        cudaEventCreateWithFlags(&evVT, cudaEventDisableTiming);
    }

    __nv_bfloat16* hhi = sym<__nv_bfloat16>(g_hhi);
    __nv_bfloat16* hlo = sym<__nv_bfloat16>(g_hlo);
    __nv_bfloat16* qhi = sym<__nv_bfloat16>(g_qhi);
    __nv_bfloat16* qlo = sym<__nv_bfloat16>(g_qlo);
    __nv_bfloat16* khi = sym<__nv_bfloat16>(g_khi);
    __nv_bfloat16* klo = sym<__nv_bfloat16>(g_klo);
    float*         v   = sym<float>(g_v);
    __nv_bfloat16* vthi= sym<__nv_bfloat16>(g_vthi);
    __nv_bfloat16* vtlo= sym<__nv_bfloat16>(g_vtlo);
    float*         sc  = sym<float>(g_sc);
    __nv_bfloat16* whi = sym<__nv_bfloat16>(g_whi);
    __nv_bfloat16* wlo = sym<__nv_bfloat16>(g_wlo);
    __nv_bfloat16* mhi = sym<__nv_bfloat16>(g_mhi);
    __nv_bfloat16* mlo = sym<__nv_bfloat16>(g_mlo);
    __nv_bfloat16* wqt = sym<__nv_bfloat16>(g_wqt);
    __nv_bfloat16* wkt = sym<__nv_bfloat16>(g_wkt);
    __nv_bfloat16* wvt = sym<__nv_bfloat16>(g_wvt);
    __nv_bfloat16* w1t = sym<__nv_bfloat16>(g_w1t);
    __nv_bfloat16* w2t = sym<__nv_bfloat16>(g_w2t);

    const size_t EE = (size_t)EDIM * EDIM;
    const size_t EM = (size_t)EDIM * MDIM;
    const cudaStream_t s0 = 0;

    dim3 tb(32, 8);

    // fork s1: W1/W2 transposes overlap the whole attention phase
    cudaEventRecord(ev0, s0);
    cudaStreamWaitEvent(s1, ev0, 0);
    transpose_split<<<dim3(MDIM/32, EDIM/32, NLAY), tb, 0, s1>>>(W1, w1t, w1t + (size_t)NLAY*EM, EDIM, MDIM, EM, EM);
    transpose_split<<<dim3(EDIM/32, MDIM/32, NLAY), tb, 0, s1>>>(W2, w2t, w2t + (size_t)NLAY*EM, MDIM, EDIM, EM, EM);
    cudaEventRecord(evW, s1);

    // main stream: QKV weight transposes + embedding
    transpose_split<<<dim3(EDIM/32, EDIM/32, 1), tb, 0, s0>>>(Wq, wqt, wqt + EE, EDIM, EDIM, 0, 0);
    transpose_split<<<dim3(EDIM/32, EDIM/32, 1), tb, 0, s0>>>(Wk, wkt, wkt + EE, EDIM, EDIM, 0, 0);
    transpose_split<<<dim3(EDIM/32, EDIM/32, 1), tb, 0, s0>>>(Wv, wvt, wvt + EE, EDIM, EDIM, 0, 0);
    embed_split<<<NROWS, 256, 0, s0>>>(x, emb, hhi, hlo);

    GP p = {};
    p.Ahi = hhi; p.Alo = hlo; p.ldA = EDIM; p.ldB = EDIM; p.ldC = EDIM;
    p.K = EDIM; p.scale = 1.f; p.relu = 0; p.maskSkip = 0; p.triK = 0;
    p.szA = p.szB = p.szC = 0;

    p.Bhi = wqt; p.Blo = wqt + EE; p.bias = bq;
    p.outHi = qhi; p.outLo = qlo; p.outF = nullptr;
    launch_gemm(p, NROWS, EDIM, 1, s0);

    p.Bhi = wkt; p.Blo = wkt + EE; p.bias = bk;
    p.outHi = khi; p.outLo = klo;
    launch_gemm(p, NROWS, EDIM, 1, s0);

    p.Bhi = wvt; p.Blo = wvt + EE; p.bias = bv;
    p.outHi = nullptr; p.outLo = nullptr; p.outF = v;
    launch_gemm(p, NROWS, EDIM, 1, s0);
    cudaEventRecord(evV, s0);

    // fork s2: v transpose overlaps the scores GEMM
    cudaStreamWaitEvent(s2, evV, 0);
    transpose_split<<<dim3(EDIM/32, SEQ/32, BATCH), tb, 0, s2>>>(v, vthi, vtlo, SEQ, EDIM,
                                                                 (size_t)SEQ*EDIM, (size_t)EDIM*SEQ);
    cudaEventRecord(evVT, s2);

    // scores = scale * q k^T  (batched, masked-tile skip)
    p.Ahi = qhi; p.Alo = qlo; p.Bhi = khi; p.Blo = klo;
    p.ldA = EDIM; p.ldB = EDIM; p.ldC = SEQ; p.K = EDIM;
    p.szA = (size_t)SEQ * EDIM; p.szB = (size_t)SEQ * EDIM; p.szC = (size_t)SEQ * SEQ;
    p.bias = nullptr; p.outF = sc; p.outHi = nullptr; p.outLo = nullptr;
    p.scale = 1.f / 32.f; p.relu = 0; p.maskSkip = 1; p.triK = 0;
    launch_gemm(p, SEQ, SEQ, BATCH, s0);

    softmax_split<<<dim3(SEQ, BATCH), 256, 0, s0>>>(sc, whi, wlo);

    // join s2 before w@v
    cudaStreamWaitEvent(s0, evVT, 0);

    // h = relu(w v)  (batched, triangular K skip)
    p.Ahi = whi; p.Alo = wlo; p.Bhi = vthi; p.Blo = vtlo;
    p.ldA = SEQ; p.ldB = SEQ; p.ldC = EDIM; p.K = SEQ;
    p.szA = (size_t)SEQ * SEQ; p.szB = (size_t)EDIM * SEQ; p.szC = (size_t)SEQ * EDIM;
    p.bias = nullptr; p.outF = nullptr; p.outHi = hhi; p.outLo = hlo;
    p.scale = 1.f; p.relu = 1; p.maskSkip = 0; p.triK = 1;
    launch_gemm(p, SEQ, EDIM, BATCH, s0);

    // join s1 before MLP
    cudaStreamWaitEvent(s0, evW, 0);

    // MLP stack
    p.szA = p.szB = p.szC = 0;
    p.maskSkip = 0; p.triK = 0;
    __nv_bfloat16 *curHi = hhi, *curLo = hlo;
    __nv_bfloat16 *altHi = qhi, *altLo = qlo;
    for (int i = 0; i < NLAY; i++) {
        p.Ahi = curHi; p.Alo = curLo;
        p.Bhi = w1t + (size_t)i * EM; p.Blo = w1t + (size_t)(NLAY + i) * EM;
        p.ldA = EDIM; p.ldB = EDIM; p.ldC = MDIM; p.K = EDIM;
        p.bias = b1 + (size_t)i * MDIM;
        p.outHi = mhi; p.outLo = mlo; p.outF = nullptr;
        p.scale = 1.f; p.relu = 1;
        launch_gemm(p, NROWS, MDIM, 1, s0);

        p.Ahi = mhi; p.Alo = mlo;
        p.Bhi = w2t + (size_t)i * EM; p.Blo = w2t + (size_t)(NLAY + i) * EM;
        p.ldA = MDIM; p.ldB = MDIM; p.ldC = EDIM; p.K = MDIM;
        p.bias = b2 + (size_t)i * EDIM;
        if (i == NLAY - 1) {
            p.outHi = nullptr; p.outLo = nullptr; p.outF = out;
        } else {
            p.outHi = altHi; p.outLo = altLo; p.outF = nullptr;
        }
        launch_gemm(p, NROWS, EDIM, 1, s0);

        __nv_bfloat16* t;
        t = curHi; curHi = altHi; altHi = t;
        t = curLo; curLo = altLo; altLo = t;
    }
}